// round 13
// baseline (speedup 1.0000x reference)
#include <cuda_runtime.h>
#include <cstdint>

// Shapes (fixed)
#define BB 32
#define TT 8192
#define II 16
#define HH 128
#define OO 3
#define PP 1024
#define CL 4
#define NTHR 576
#define HXF 160      // floats per ring slot: [0..15]=x, [16..47]=h_local, [48..143]=h_remote
#define VX 0
#define VHL 16
#define VHR 48

// Shared layout (float offsets unless noted)
#define OFF_HXA 0                 // ring A: 3*160 = 480
#define OFF_HXB 480               // ring B: 3*160 = 480 -> 960
#define OFF_MBAR_BYTES 3840       // A: +8s (s=0..2), B: +24+8s  (48 bytes total)
#define OFF_SUMS_A 972
#define OFF_CNT_A  4044
#define OFF_SUMS_B 5068
#define OFF_CNT_B  8140
#define SMEM_FLOATS 9164
#define TXB 384u                  // per barrier per phase: 3 peers x 32 floats
#define HXB_BYTE 1920u            // OFF_HXB*4

typedef unsigned long long u64;

__device__ __forceinline__ uint32_t smem_u32(const void* p) {
    uint32_t a;
    asm("{ .reg .u64 t; cvta.to.shared.u64 t, %1; cvt.u32.u64 %0, t; }"
        : "=r"(a) : "l"(p));
    return a;
}
__device__ __forceinline__ uint32_t mapa_u32(uint32_t a, uint32_t r) {
    uint32_t d;
    asm("mapa.shared::cluster.u32 %0, %1, %2;" : "=r"(d) : "r"(a), "r"(r));
    return d;
}
__device__ __forceinline__ void mbar_init(uint32_t mbar, uint32_t cnt) {
    asm volatile("mbarrier.init.shared.b64 [%0], %1;" :: "r"(mbar), "r"(cnt) : "memory");
}
__device__ __forceinline__ void mbar_expect_tx(uint32_t mbar, uint32_t tx) {
    asm volatile("mbarrier.arrive.expect_tx.shared.b64 _, [%0], %1;"
                 :: "r"(mbar), "r"(tx) : "memory");
}
__device__ __forceinline__ void mbar_wait(uint32_t mbar, unsigned parity) {
    asm volatile(
        "{\n\t.reg .pred P;\n"
        "W%=:\n\t"
        "mbarrier.try_wait.parity.acquire.cta.shared::cta.b64 P, [%0], %1, 10000000;\n\t"
        "@!P bra W%=;\n\t"
        "}" :: "r"(mbar), "r"(parity) : "memory");
}
__device__ __forceinline__ void st_async_b32(uint32_t addr, float v, uint32_t mbar) {
    asm volatile("st.async.shared::cluster.mbarrier::complete_tx::bytes.b32 [%0], %1, [%2];"
                 :: "r"(addr), "r"(__float_as_uint(v)), "r"(mbar) : "memory");
}
__device__ __forceinline__ u64 pack2(float lo, float hi) {
    u64 p;
    asm("mov.b64 %0, {%1, %2};" : "=l"(p) : "r"(__float_as_uint(lo)), "r"(__float_as_uint(hi)));
    return p;
}
__device__ __forceinline__ void unpack2(float& lo, float& hi, u64 p) {
    uint32_t a, b;
    asm("mov.b64 {%0, %1}, %2;" : "=r"(a), "=r"(b) : "l"(p));
    lo = __uint_as_float(a); hi = __uint_as_float(b);
}
__device__ __forceinline__ u64 ffma2(u64 a, u64 b, u64 c) {
    u64 d;
    asm("fma.rn.f32x2 %0, %1, %2, %3;" : "=l"(d) : "l"(a), "l"(b), "l"(c));
    return d;
}
__device__ __forceinline__ float tanh_ap(float v) {
    float y;
    asm("tanh.approx.f32 %0, %1;" : "=f"(y) : "f"(v));
    return y;
}
__device__ __forceinline__ float sig_ap(float v) {
    return fmaf(0.5f, tanh_ap(0.5f * v), 0.5f);
}

__global__ void __launch_bounds__(NTHR, 1) __cluster_dims__(CL, 1, 1)
lstm_dual_kernel(const float* __restrict__ x,
                 const float* __restrict__ W_ih,
                 const float* __restrict__ W_hh,
                 const float* __restrict__ b_ih,
                 const float* __restrict__ b_hh,
                 const float* __restrict__ W_fc,
                 const float* __restrict__ b_fc,
                 float* __restrict__ out) {
    __shared__ __align__(16) float smf[SMEM_FLOATS];
    const int tid  = threadIdx.x;
    const int warp = tid >> 5;
    const int lane = tid & 31;
    uint32_t R;
    asm("mov.u32 %0, %%cluster_ctarank;" : "=r"(R));
    const int b0 = (blockIdx.x >> 2) * 2;
    const int b1 = b0 + 1;

    const uint32_t sbase = smem_u32(smf);
    uint32_t pbase[CL];
#pragma unroll
    for (int c = 0; c < CL; c++) pbase[c] = mapa_u32(sbase, (uint32_t)c);

    // ---- Prologue ----
    for (int i = tid + OFF_SUMS_A; i < SMEM_FLOATS; i += NTHR) smf[i] = 0.0f;
    if (tid == 0) {
#pragma unroll
        for (int s = 0; s < 3; s++) {
            mbar_init(sbase + OFF_MBAR_BYTES + 8 * s, 1);        // A
            mbar_init(sbase + OFF_MBAR_BYTES + 24 + 8 * s, 1);   // B
        }
    }
    if (tid < HXF) {
        smf[OFF_HXA + tid] = (tid < II) ? x[((size_t)b0 * TT) * II + tid] : 0.0f;
        smf[OFF_HXB + tid] = (tid < II) ? x[((size_t)b1 * TT) * II + tid] : 0.0f;
    }
    __syncthreads();
    asm volatile("barrier.cluster.arrive.aligned;" ::: "memory");
    asm volatile("barrier.cluster.wait.aligned;" ::: "memory");

    // ---- Matvec role prologue (weights shared across both batches) ----
    // lane = rowhalf*16 + gate*4 + j ; hl2 = 2*warp + rowhalf ; row = gate*128 + 32R + hl2.
    // Thread j covers local v[12j..12j+12) and remote v[48+24j..48+24j+24).
    u64   w2l[6], w2r[12];
    u64   biasPack = 0;
    u64   aA0 = 0, aB0 = 0, aA1 = 0, aB1 = 0;     // shadow partials for A, B
    float cA = 0.0f, cB = 0.0f;
    int   j = 0;
    uint32_t peerh[3], peerm[3];
    const bool owner = (tid < 512) && ((lane & 15) == 0);
    if (tid < 512) {
        j = lane & 3;
        const int gate = (lane >> 2) & 3;
        const int hl2  = 2 * warp + (lane >> 4);
        const int row  = gate * HH + 32 * (int)R + hl2;
        float wl[12], wr[24];
#pragma unroll
        for (int m = 0; m < 12; m++) {
            const int p = 12 * j + m;
            wl[m] = (p < 16) ? W_ih[(size_t)row * II + p]
                             : W_hh[(size_t)row * HH + 32 * (int)R + (p - 16)];
        }
#pragma unroll
        for (int m = 0; m < 24; m++) {
            const int q = 24 * j + m;
            int sr = q >> 5;
            const int r = (sr < (int)R) ? sr : sr + 1;
            wr[m] = W_hh[(size_t)row * HH + 32 * r + (q & 31)];
        }
#pragma unroll
        for (int m = 0; m < 6; m++)  w2l[m] = pack2(wl[2 * m], wl[2 * m + 1]);
#pragma unroll
        for (int m = 0; m < 12; m++) w2r[m] = pack2(wr[2 * m], wr[2 * m + 1]);
        if (j == 0) biasPack = pack2(b_ih[row] + b_hh[row], 0.0f);
        if (owner) {
            const int hoff = 2 * warp + (lane >> 4);
#pragma unroll
            for (int c3 = 0; c3 < 3; c3++) {
                const int c  = (int)((R + 1 + c3) & 3);
                const int ix = ((int)R < c) ? (int)R : (int)R - 1;
                peerh[c3] = pbase[c] + (uint32_t)((OFF_HXA + VHR + 32 * ix + hoff) * 4);
                peerm[c3] = pbase[c] + OFF_MBAR_BYTES;
            }
        }
        // Pre-loop shadow partials over slot 0 of each ring
#pragma unroll
        for (int bb = 0; bb < 2; bb++) {
            const ulonglong2* hlp =
                (const ulonglong2*)(smf + (bb ? OFF_HXB : OFF_HXA) + 12 * j);
            u64 aA = biasPack, aB = 0;
#pragma unroll
            for (int m = 0; m < 3; m++) {
                ulonglong2 h2 = hlp[m];
                aA = ffma2(w2l[2 * m],     h2.x, aA);
                aB = ffma2(w2l[2 * m + 1], h2.y, aB);
            }
            if (bb == 0) { aA0 = aA; aB0 = aB; } else { aA1 = aA; aB1 = aB; }
        }
    }
    // FC warp (16)
    float wfc0 = 0.f, wfc1 = 0.f, wfc2 = 0.f, bfc0 = 0.f, bfc1 = 0.f, bfc2 = 0.f;
    if (warp == 16) {
        const int hi = 32 * (int)R + lane;
        wfc0 = W_fc[hi]; wfc1 = W_fc[HH + hi]; wfc2 = W_fc[2 * HH + hi];
        if (R == 0 && lane == 0) { bfc0 = b_fc[0]; bfc1 = b_fc[1]; bfc2 = b_fc[2]; }
    }
    // Comm warp (17): lanes 0..7 x(t+1) for batch A, lanes 8..15 for batch B
    float2 xr = make_float2(0.f, 0.f);
    if (warp == 17 && lane < 16) {
        const int bb = (lane >> 3);
        xr = ((const float2*)(x + ((size_t)(b0 + bb) * TT + 1) * II))[lane & 7];
    }

    int pidA = 0, pidB = 0;
    unsigned par0 = 0, par1 = 0, par2 = 0;
    int cur = 0;

    // ---- Time loop: one iteration = one step of batch A + one step of batch B ----
    for (int t = 0; t < TT; t++) {
        int nxt = cur + 1; if (nxt == 3) nxt = 0;
        const uint32_t slotB = (uint32_t)(nxt * HXF * 4);

        if (tid < 512) {
            const unsigned parity = (cur == 0) ? par0 : ((cur == 1) ? par1 : par2);
            // ===== batch A =====
            if (t > 0) mbar_wait(sbase + OFF_MBAR_BYTES + 8 * cur, parity);
            {
                const float* hxc = smf + OFF_HXA + cur * HXF;
                u64 aA = aA0, aB = aB0;
                const ulonglong2* hr = (const ulonglong2*)(hxc + VHR + 24 * j);
#pragma unroll
                for (int m = 0; m < 6; m++) {
                    ulonglong2 h2 = hr[m];
                    aA = ffma2(w2r[2 * m],     h2.x, aA);
                    aB = ffma2(w2r[2 * m + 1], h2.y, aB);
                }
                float a0, a1, a2, a3;
                unpack2(a0, a1, aA); unpack2(a2, a3, aB);
                float pre = (a0 + a1) + (a2 + a3);
                pre += __shfl_xor_sync(0xffffffffu, pre, 1);
                pre += __shfl_xor_sync(0xffffffffu, pre, 2);
                const int gate = (lane >> 2) & 3;
                float act = (gate == 2) ? tanh_ap(pre) : sig_ap(pre);
                const int g16 = lane & 16;
                float vi = __shfl_sync(0xffffffffu, act, g16);
                float vf = __shfl_sync(0xffffffffu, act, g16 + 4);
                float vg = __shfl_sync(0xffffffffu, act, g16 + 8);
                float vo = __shfl_sync(0xffffffffu, act, g16 + 12);
                if (owner) {
                    cA = fmaf(vf, cA, vi * vg);
                    float hval = vo * tanh_ap(cA);
#pragma unroll
                    for (int c3 = 0; c3 < 3; c3++)
                        st_async_b32(peerh[c3] + slotB, hval, peerm[c3] + 8 * nxt);
                    smf[OFF_HXA + nxt * HXF + VHL + 2 * warp + (lane >> 4)] = hval;
                }
            }
            // ===== batch B =====
            if (t > 0) mbar_wait(sbase + OFF_MBAR_BYTES + 24 + 8 * cur, parity);
            {
                const float* hxc = smf + OFF_HXB + cur * HXF;
                u64 aA = aA1, aB = aB1;
                const ulonglong2* hr = (const ulonglong2*)(hxc + VHR + 24 * j);
#pragma unroll
                for (int m = 0; m < 6; m++) {
                    ulonglong2 h2 = hr[m];
                    aA = ffma2(w2r[2 * m],     h2.x, aA);
                    aB = ffma2(w2r[2 * m + 1], h2.y, aB);
                }
                float a0, a1, a2, a3;
                unpack2(a0, a1, aA); unpack2(a2, a3, aB);
                float pre = (a0 + a1) + (a2 + a3);
                pre += __shfl_xor_sync(0xffffffffu, pre, 1);
                pre += __shfl_xor_sync(0xffffffffu, pre, 2);
                const int gate = (lane >> 2) & 3;
                float act = (gate == 2) ? tanh_ap(pre) : sig_ap(pre);
                const int g16 = lane & 16;
                float vi = __shfl_sync(0xffffffffu, act, g16);
                float vf = __shfl_sync(0xffffffffu, act, g16 + 4);
                float vg = __shfl_sync(0xffffffffu, act, g16 + 8);
                float vo = __shfl_sync(0xffffffffu, act, g16 + 12);
                if (owner) {
                    cB = fmaf(vf, cB, vi * vg);
                    float hval = vo * tanh_ap(cB);
#pragma unroll
                    for (int c3 = 0; c3 < 3; c3++)
                        st_async_b32(peerh[c3] + HXB_BYTE + slotB, hval,
                                     peerm[c3] + 24 + 8 * nxt);
                    smf[OFF_HXB + nxt * HXF + VHL + 2 * warp + (lane >> 4)] = hval;
                }
            }
            if (t > 0) {
                if (cur == 0) par0 ^= 1; else if (cur == 1) par1 ^= 1; else par2 ^= 1;
            }
        } else if (warp == 16) {
            const float* hA = smf + OFF_HXA + cur * HXF;
            const float* hB = smf + OFF_HXB + cur * HXF;
            const int pidA_n = (int)hA[VX + 2];
            const int pidB_n = (int)hB[VX + 2];
            if (t > 0) {
                float hvA = hA[VHL + lane];
                float hvB = hB[VHL + lane];
                float p0 = hvA * wfc0, p1 = hvA * wfc1, p2 = hvA * wfc2;
                float q0 = hvB * wfc0, q1 = hvB * wfc1, q2 = hvB * wfc2;
#pragma unroll
                for (int o = 16; o > 0; o >>= 1) {
                    p0 += __shfl_down_sync(0xffffffffu, p0, o);
                    p1 += __shfl_down_sync(0xffffffffu, p1, o);
                    p2 += __shfl_down_sync(0xffffffffu, p2, o);
                    q0 += __shfl_down_sync(0xffffffffu, q0, o);
                    q1 += __shfl_down_sync(0xffffffffu, q1, o);
                    q2 += __shfl_down_sync(0xffffffffu, q2, o);
                }
                if (lane == 0) {
                    if ((unsigned)pidA < PP) {
                        float* s = &smf[OFF_SUMS_A + pidA * 3];
                        s[0] += p0 + bfc0; s[1] += p1 + bfc1; s[2] += p2 + bfc2;
                        if (R == 0) smf[OFF_CNT_A + pidA] += 1.0f;
                    }
                    if ((unsigned)pidB < PP) {
                        float* s = &smf[OFF_SUMS_B + pidB * 3];
                        s[0] += q0 + bfc0; s[1] += q1 + bfc1; s[2] += q2 + bfc2;
                        if (R == 0) smf[OFF_CNT_B + pidB] += 1.0f;
                    }
                }
            }
            pidA = pidA_n; pidB = pidB_n;
        } else {
            // Comm warp: expect_tx both barriers; stage x(t+1) for both batches
            if (lane == 16) {
                mbar_expect_tx(sbase + OFF_MBAR_BYTES + 8 * nxt, TXB);
            } else if (lane == 17) {
                mbar_expect_tx(sbase + OFF_MBAR_BYTES + 24 + 8 * nxt, TXB);
            } else if (lane < 16) {
                const int bb = lane >> 3;
                const int l8 = lane & 7;
                *(float2*)&smf[(bb ? OFF_HXB : OFF_HXA) + nxt * HXF + VX + 2 * l8] = xr;
                xr = (t + 2 < TT)
                   ? ((const float2*)(x + ((size_t)(b0 + bb) * TT + t + 2) * II))[l8]
                   : make_float2(0.f, 0.f);
            }
        }
        __syncthreads();
        // Shadow: local partial dots for step t+1, both rings (slot nxt)
        if (tid < 512) {
#pragma unroll
            for (int bb = 0; bb < 2; bb++) {
                const ulonglong2* hlp =
                    (const ulonglong2*)(smf + (bb ? OFF_HXB : OFF_HXA) + nxt * HXF + 12 * j);
                u64 aA = biasPack, aB = 0;
#pragma unroll
                for (int m = 0; m < 3; m++) {
                    ulonglong2 h2 = hlp[m];
                    aA = ffma2(w2l[2 * m],     h2.x, aA);
                    aB = ffma2(w2l[2 * m + 1], h2.y, aB);
                }
                if (bb == 0) { aA0 = aA; aB0 = aB; } else { aA1 = aA; aB1 = aB; }
            }
        }
        cur = nxt;
    }

    // ---- Final FC round for h(TT-1): slot 2 local regions ----
    if (warp == 16) {
        const float* hA = smf + OFF_HXA + 2 * HXF;
        const float* hB = smf + OFF_HXB + 2 * HXF;
        float hvA = hA[VHL + lane];
        float hvB = hB[VHL + lane];
        float p0 = hvA * wfc0, p1 = hvA * wfc1, p2 = hvA * wfc2;
        float q0 = hvB * wfc0, q1 = hvB * wfc1, q2 = hvB * wfc2;
#pragma unroll
        for (int o = 16; o > 0; o >>= 1) {
            p0 += __shfl_down_sync(0xffffffffu, p0, o);
            p1 += __shfl_down_sync(0xffffffffu, p1, o);
            p2 += __shfl_down_sync(0xffffffffu, p2, o);
            q0 += __shfl_down_sync(0xffffffffu, q0, o);
            q1 += __shfl_down_sync(0xffffffffu, q1, o);
            q2 += __shfl_down_sync(0xffffffffu, q2, o);
        }
        if (lane == 0) {
            if ((unsigned)pidA < PP) {
                float* s = &smf[OFF_SUMS_A + pidA * 3];
                s[0] += p0 + bfc0; s[1] += p1 + bfc1; s[2] += p2 + bfc2;
                if (R == 0) smf[OFF_CNT_A + pidA] += 1.0f;
            }
            if ((unsigned)pidB < PP) {
                float* s = &smf[OFF_SUMS_B + pidB * 3];
                s[0] += q0 + bfc0; s[1] += q1 + bfc1; s[2] += q2 + bfc2;
                if (R == 0) smf[OFF_CNT_B + pidB] += 1.0f;
            }
        }
    }
    __syncthreads();
    asm volatile("barrier.cluster.arrive.aligned;" ::: "memory");
    asm volatile("barrier.cluster.wait.aligned;" ::: "memory");

    // ---- Epilogue: rank 0 gathers peer partial sums via DSMEM, writes both batches ----
    if (R == 0) {
        for (int idx = tid; idx < PP * OO; idx += NTHR) {
            const int p = idx / 3;
            float sA = smf[OFF_SUMS_A + idx];
            float sB = smf[OFF_SUMS_B + idx];
#pragma unroll
            for (int c = 1; c < CL; c++) {
                float vA, vB;
                const uint32_t raA = pbase[c] + (uint32_t)((OFF_SUMS_A + idx) * 4);
                const uint32_t raB = pbase[c] + (uint32_t)((OFF_SUMS_B + idx) * 4);
                asm volatile("ld.shared::cluster.f32 %0, [%1];" : "=f"(vA) : "r"(raA));
                asm volatile("ld.shared::cluster.f32 %0, [%1];" : "=f"(vB) : "r"(raB));
                sA += vA; sB += vB;
            }
            float ccA = smf[OFF_CNT_A + p]; if (ccA == 0.0f) ccA = 1.0f;
            float ccB = smf[OFF_CNT_B + p]; if (ccB == 0.0f) ccB = 1.0f;
            out[(size_t)b0 * PP * OO + idx] = sA / ccA;
            out[(size_t)b1 * PP * OO + idx] = sB / ccB;
        }
    }
    asm volatile("barrier.cluster.arrive.aligned;" ::: "memory");
    asm volatile("barrier.cluster.wait.aligned;" ::: "memory");
}

extern "C" void kernel_launch(void* const* d_in, const int* in_sizes, int n_in,
                              void* d_out, int out_size) {
    const float* x    = (const float*)d_in[0];
    const float* W_ih = (const float*)d_in[1];
    const float* W_hh = (const float*)d_in[2];
    const float* b_ih = (const float*)d_in[3];
    const float* b_hh = (const float*)d_in[4];
    const float* W_fc = (const float*)d_in[5];
    const float* b_fc = (const float*)d_in[6];
    float* out = (float*)d_out;
    lstm_dual_kernel<<<(BB / 2) * CL, NTHR>>>(x, W_ih, W_hh, b_ih, b_hh, W_fc, b_fc, out);
}

// round 16
// speedup vs baseline: 1.8749x; 1.8749x over previous
#include <cuda_runtime.h>
#include <cstdint>

// Shapes (fixed)
#define BB 32
#define TT 8192
#define II 16
#define HH 128
#define OO 3
#define PP 1024
#define CL 4
#define NTHR 576
#define HXF 160      // floats per ring slot: [0..15]=x, [16..47]=h_local, [48..143]=h_remote
#define VX 0
#define VHL 16
#define VHR 48

// Shared layout (float offsets unless noted)
#define OFF_HX 0                  // 3 * 160 = 480
#define OFF_MBAR_BYTES 1920       // bytes 1920..1943 (3 x 8B)
#define OFF_SUMS 488
#define OFF_CNT  3560
#define SMEM_FLOATS 4584
#define TXB 384u                  // 3 peers x 32 floats = 384 B per slot per phase

typedef unsigned long long u64;

__device__ __forceinline__ uint32_t smem_u32(const void* p) {
    uint32_t a;
    asm("{ .reg .u64 t; cvta.to.shared.u64 t, %1; cvt.u32.u64 %0, t; }"
        : "=r"(a) : "l"(p));
    return a;
}
__device__ __forceinline__ uint32_t mapa_u32(uint32_t a, uint32_t r) {
    uint32_t d;
    asm("mapa.shared::cluster.u32 %0, %1, %2;" : "=r"(d) : "r"(a), "r"(r));
    return d;
}
__device__ __forceinline__ void mbar_init(uint32_t mbar, uint32_t cnt) {
    asm volatile("mbarrier.init.shared.b64 [%0], %1;" :: "r"(mbar), "r"(cnt) : "memory");
}
__device__ __forceinline__ void mbar_expect_tx(uint32_t mbar, uint32_t tx) {
    asm volatile("mbarrier.arrive.expect_tx.shared.b64 _, [%0], %1;"
                 :: "r"(mbar), "r"(tx) : "memory");
}
__device__ __forceinline__ void mbar_wait(uint32_t mbar, unsigned parity) {
    asm volatile(
        "{\n\t.reg .pred P;\n"
        "W%=:\n\t"
        "mbarrier.try_wait.parity.acquire.cta.shared::cta.b64 P, [%0], %1, 10000000;\n\t"
        "@!P bra W%=;\n\t"
        "}" :: "r"(mbar), "r"(parity) : "memory");
}
__device__ __forceinline__ void st_async_b32(uint32_t addr, float v, uint32_t mbar) {
    asm volatile("st.async.shared::cluster.mbarrier::complete_tx::bytes.b32 [%0], %1, [%2];"
                 :: "r"(addr), "r"(__float_as_uint(v)), "r"(mbar) : "memory");
}
__device__ __forceinline__ u64 pack2(float lo, float hi) {
    u64 p;
    asm("mov.b64 %0, {%1, %2};" : "=l"(p) : "r"(__float_as_uint(lo)), "r"(__float_as_uint(hi)));
    return p;
}
__device__ __forceinline__ void unpack2(float& lo, float& hi, u64 p) {
    uint32_t a, b;
    asm("mov.b64 {%0, %1}, %2;" : "=r"(a), "=r"(b) : "l"(p));
    lo = __uint_as_float(a); hi = __uint_as_float(b);
}
__device__ __forceinline__ u64 ffma2(u64 a, u64 b, u64 c) {
    u64 d;
    asm("fma.rn.f32x2 %0, %1, %2, %3;" : "=l"(d) : "l"(a), "l"(b), "l"(c));
    return d;
}
__device__ __forceinline__ float tanh_ap(float v) {
    float y;
    asm("tanh.approx.f32 %0, %1;" : "=f"(y) : "f"(v));
    return y;
}
__device__ __forceinline__ float sig_ap(float v) {
    return fmaf(0.5f, tanh_ap(0.5f * v), 0.5f);
}

__global__ void __launch_bounds__(NTHR, 1) __cluster_dims__(CL, 1, 1)
lstm_coal_kernel(const float* __restrict__ x,
                 const float* __restrict__ W_ih,
                 const float* __restrict__ W_hh,
                 const float* __restrict__ b_ih,
                 const float* __restrict__ b_hh,
                 const float* __restrict__ W_fc,
                 const float* __restrict__ b_fc,
                 float* __restrict__ out) {
    __shared__ __align__(16) float smf[SMEM_FLOATS];
    const int tid  = threadIdx.x;
    const int warp = tid >> 5;
    const int lane = tid & 31;
    uint32_t R;
    asm("mov.u32 %0, %%cluster_ctarank;" : "=r"(R));
    const int b = blockIdx.x >> 2;

    const uint32_t sbase = smem_u32(smf);
    uint32_t pbase[CL];
#pragma unroll
    for (int c = 0; c < CL; c++) pbase[c] = mapa_u32(sbase, (uint32_t)c);

    // ---- Prologue: accumulators, barriers, slot 0 = [x(0) | zeros] ----
    for (int i = tid; i < PP * OO; i += NTHR) smf[OFF_SUMS + i] = 0.0f;
    for (int i = tid; i < PP; i += NTHR)      smf[OFF_CNT + i]  = 0.0f;
    if (tid == 0) {
#pragma unroll
        for (int s = 0; s < 3; s++) mbar_init(sbase + OFF_MBAR_BYTES + 8 * s, 1);
    }
    if (tid < II)                    smf[OFF_HX + VX + tid]  = x[((size_t)b * TT) * II + tid];
    if (tid >= II && tid < HXF - 16) smf[OFF_HX + tid]       = 0.0f;   // h_local+h_remote = 0
    __syncthreads();
    asm volatile("barrier.cluster.arrive.aligned;" ::: "memory");
    asm volatile("barrier.cluster.wait.aligned;" ::: "memory");

    // ---- Matvec role prologue ----
    // lane = rowhalf*16 + gate*4 + j ; hl2 = 2*warp + rowhalf ; row = gate*128 + 32R + hl2.
    // INTERLEAVED k-partition: thread j owns float4 chunk c = j + 4m.
    //   local  (48 floats = 12 chunks): m = 0..2, positions p = 4*(j+4m)+e
    //   remote (96 floats = 24 chunks): m = 0..5, positions q = 4*(j+4m)+e
    // => per-LDS distinct addrs {0,16,32,48}+64m bytes: ONE 128B line.
    u64   w2l[6], w2r[12];
    u64   biasPack = 0, aLA = 0, aLB = 0;
    float c_state = 0.0f;
    int   j = 0;
    uint32_t peerh[3], peerm[3];
    const bool owner = (tid < 512) && ((lane & 15) == 0);
    if (tid < 512) {
        j = lane & 3;
        const int gate = (lane >> 2) & 3;
        const int hl2  = 2 * warp + (lane >> 4);
        const int row  = gate * HH + 32 * (int)R + hl2;
        float wl[12], wr[24];
#pragma unroll
        for (int m = 0; m < 3; m++) {
#pragma unroll
            for (int e = 0; e < 4; e++) {
                const int p = 4 * (j + 4 * m) + e;
                wl[4 * m + e] = (p < 16) ? W_ih[(size_t)row * II + p]
                                         : W_hh[(size_t)row * HH + 32 * (int)R + (p - 16)];
            }
        }
#pragma unroll
        for (int m = 0; m < 6; m++) {
#pragma unroll
            for (int e = 0; e < 4; e++) {
                const int q  = 4 * (j + 4 * m) + e;
                const int sr = q >> 5;                      // sender slot 0..2
                const int r  = (sr < (int)R) ? sr : sr + 1; // actual sender rank
                wr[4 * m + e] = W_hh[(size_t)row * HH + 32 * r + (q & 31)];
            }
        }
#pragma unroll
        for (int m = 0; m < 6; m++)  w2l[m] = pack2(wl[2 * m], wl[2 * m + 1]);
#pragma unroll
        for (int m = 0; m < 12; m++) w2r[m] = pack2(wr[2 * m], wr[2 * m + 1]);
        if (j == 0) biasPack = pack2(b_ih[row] + b_hh[row], 0.0f);
        if (owner) {
            const int hoff = 2 * warp + (lane >> 4);
#pragma unroll
            for (int c3 = 0; c3 < 3; c3++) {
                const int c  = (int)((R + 1 + c3) & 3);
                const int ix = ((int)R < c) ? (int)R : (int)R - 1;
                peerh[c3] = pbase[c] + (uint32_t)((OFF_HX + VHR + 32 * ix + hoff) * 4);
                peerm[c3] = pbase[c] + OFF_MBAR_BYTES;
            }
        }
        // Pre-loop: local partial for step 0 over slot 0 (x(0), h_local=0)
        const ulonglong2* hlp = (const ulonglong2*)(smf + OFF_HX);
        u64 aA = biasPack, aB = 0;
#pragma unroll
        for (int m = 0; m < 3; m++) {
            ulonglong2 h2 = hlp[j + 4 * m];
            aA = ffma2(w2l[2 * m],     h2.x, aA);
            aB = ffma2(w2l[2 * m + 1], h2.y, aB);
        }
        aLA = aA; aLB = aB;
    }
    // FC warp (16)
    float wfc0 = 0.f, wfc1 = 0.f, wfc2 = 0.f, bfc0 = 0.f, bfc1 = 0.f, bfc2 = 0.f;
    if (warp == 16) {
        const int hi = 32 * (int)R + lane;
        wfc0 = W_fc[hi]; wfc1 = W_fc[HH + hi]; wfc2 = W_fc[2 * HH + hi];
        if (R == 0 && lane == 0) { bfc0 = b_fc[0]; bfc1 = b_fc[1]; bfc2 = b_fc[2]; }
    }
    // Comm warp (17): lanes 0..7 hold x(t+1) as float2
    float2 xr = make_float2(0.f, 0.f);
    if (warp == 17 && lane < 8)
        xr = ((const float2*)(x + ((size_t)b * TT + 1) * II))[lane];

    int pid = 0;
    unsigned par0 = 0, par1 = 0, par2 = 0;
    int cur = 0;

    // ---- Time loop ----
    for (int t = 0; t < TT; t++) {
        int nxt = cur + 1; if (nxt == 3) nxt = 0;
        const float* hxc = smf + OFF_HX + cur * HXF;
        const uint32_t mbo = (uint32_t)(OFF_MBAR_BYTES + 8 * nxt);

        if (tid < 512) {
            if (t > 0) {
                unsigned parity = (cur == 0) ? par0 : ((cur == 1) ? par1 : par2);
                mbar_wait(sbase + OFF_MBAR_BYTES + 8 * cur, parity);
                if (cur == 0) par0 ^= 1; else if (cur == 1) par1 ^= 1; else par2 ^= 1;
            }
            // Remote dot (96 wide) on top of saved local partial; interleaved chunks
            u64 aA = aLA, aB = aLB;
            const ulonglong2* hr = (const ulonglong2*)(hxc + VHR);
#pragma unroll
            for (int m = 0; m < 6; m++) {
                ulonglong2 h2 = hr[j + 4 * m];
                aA = ffma2(w2r[2 * m],     h2.x, aA);
                aB = ffma2(w2r[2 * m + 1], h2.y, aB);
            }
            float a0, a1, a2, a3;
            unpack2(a0, a1, aA);
            unpack2(a2, a3, aB);
            float pre = (a0 + a1) + (a2 + a3);
            pre += __shfl_xor_sync(0xffffffffu, pre, 1);
            pre += __shfl_xor_sync(0xffffffffu, pre, 2);
            const int gate = (lane >> 2) & 3;
            float act = (gate == 2) ? tanh_ap(pre) : sig_ap(pre);
            const int b16 = lane & 16;
            float vi = __shfl_sync(0xffffffffu, act, b16);
            float vf = __shfl_sync(0xffffffffu, act, b16 + 4);
            float vg = __shfl_sync(0xffffffffu, act, b16 + 8);
            float vo = __shfl_sync(0xffffffffu, act, b16 + 12);
            if (owner) {                      // lanes 0,16 own h[2*warp + (lane>>4)]
                c_state = fmaf(vf, c_state, vi * vg);
                float hval = vo * tanh_ap(c_state);
                const uint32_t slotB = (uint32_t)(nxt * HXF * 4);
#pragma unroll
                for (int c3 = 0; c3 < 3; c3++)
                    st_async_b32(peerh[c3] + slotB, hval, peerm[c3] + 8 * nxt);
                // local h_local STS (ordered by the syncthreads below)
                smf[OFF_HX + nxt * HXF + VHL + 2 * warp + (lane >> 4)] = hval;
            }
        } else if (warp == 16) {
            // FC for h(t-1): slot cur local region; pid captured last step from x(t-1)[2]
            const int pid_next = (int)hxc[VX + 2];    // x(t)[2]
            if (t > 0) {
                float hv = hxc[VHL + lane];
                float p0 = hv * wfc0, p1 = hv * wfc1, p2 = hv * wfc2;
#pragma unroll
                for (int o = 16; o > 0; o >>= 1) {
                    p0 += __shfl_down_sync(0xffffffffu, p0, o);
                    p1 += __shfl_down_sync(0xffffffffu, p1, o);
                    p2 += __shfl_down_sync(0xffffffffu, p2, o);
                }
                if (lane == 0 && (unsigned)pid < PP) {
                    float* s = &smf[OFF_SUMS + pid * 3];
                    s[0] += p0 + bfc0; s[1] += p1 + bfc1; s[2] += p2 + bfc2;
                    if (R == 0) smf[OFF_CNT + pid] += 1.0f;
                }
            }
            pid = pid_next;
        } else {
            // Comm warp: x(t+1) into slot nxt (plain STS), expect_tx(nxt), prefetch x(t+2)
            if (lane == 16) {
                mbar_expect_tx(sbase + mbo, TXB);
            } else if (lane < 8) {
                *(float2*)&smf[OFF_HX + nxt * HXF + VX + 2 * lane] = xr;
                xr = (t + 2 < TT)
                   ? ((const float2*)(x + ((size_t)b * TT + t + 2) * II))[lane]
                   : make_float2(0.f, 0.f);
            }
        }
        __syncthreads();
        // Shadow work: local partial dot for step t+1 over slot nxt [x(t+1) | h_local(t)]
        if (tid < 512) {
            const ulonglong2* hlp = (const ulonglong2*)(smf + OFF_HX + nxt * HXF);
            u64 aA = biasPack, aB = 0;
#pragma unroll
            for (int m = 0; m < 3; m++) {
                ulonglong2 h2 = hlp[j + 4 * m];
                aA = ffma2(w2l[2 * m],     h2.x, aA);
                aB = ffma2(w2l[2 * m + 1], h2.y, aB);
            }
            aLA = aA; aLB = aB;
        }
        cur = nxt;
    }

    // ---- Final FC round for h(TT-1): slot 2 local region (8191%3==1 -> nxt==2) ----
    if (warp == 16) {
        const float* hxc = smf + OFF_HX + 2 * HXF;
        float hv = hxc[VHL + lane];
        float p0 = hv * wfc0, p1 = hv * wfc1, p2 = hv * wfc2;
#pragma unroll
        for (int o = 16; o > 0; o >>= 1) {
            p0 += __shfl_down_sync(0xffffffffu, p0, o);
            p1 += __shfl_down_sync(0xffffffffu, p1, o);
            p2 += __shfl_down_sync(0xffffffffu, p2, o);
        }
        if (lane == 0 && (unsigned)pid < PP) {
            float* s = &smf[OFF_SUMS + pid * 3];
            s[0] += p0 + bfc0; s[1] += p1 + bfc1; s[2] += p2 + bfc2;
            if (R == 0) smf[OFF_CNT + pid] += 1.0f;
        }
    }
    __syncthreads();
    asm volatile("barrier.cluster.arrive.aligned;" ::: "memory");
    asm volatile("barrier.cluster.wait.aligned;" ::: "memory");

    // ---- Epilogue: rank 0 gathers peer partial sums via DSMEM, writes out ----
    if (R == 0) {
        for (int idx = tid; idx < PP * OO; idx += NTHR) {
            float s = smf[OFF_SUMS + idx];
#pragma unroll
            for (int c = 1; c < CL; c++) {
                const uint32_t ra = pbase[c] + (uint32_t)((OFF_SUMS + idx) * 4);
                float v;
                asm volatile("ld.shared::cluster.f32 %0, [%1];" : "=f"(v) : "r"(ra));
                s += v;
            }
            const int p = idx / 3;
            float cc = smf[OFF_CNT + p];
            if (cc == 0.0f) cc = 1.0f;
            out[(size_t)b * PP * OO + idx] = s / cc;
        }
    }
    asm volatile("barrier.cluster.arrive.aligned;" ::: "memory");
    asm volatile("barrier.cluster.wait.aligned;" ::: "memory");
}

extern "C" void kernel_launch(void* const* d_in, const int* in_sizes, int n_in,
                              void* d_out, int out_size) {
    const float* x    = (const float*)d_in[0];
    const float* W_ih = (const float*)d_in[1];
    const float* W_hh = (const float*)d_in[2];
    const float* b_ih = (const float*)d_in[3];
    const float* b_hh = (const float*)d_in[4];
    const float* W_fc = (const float*)d_in[5];
    const float* b_fc = (const float*)d_in[6];
    float* out = (float*)d_out;
    lstm_coal_kernel<<<BB * CL, NTHR>>>(x, W_ih, W_hh, b_ih, b_hh, W_fc, b_fc, out);
}